// round 5
// baseline (speedup 1.0000x reference)
#include <cuda_runtime.h>
#include <cuda_bf16.h>
#include <cstdint>
#include <cstddef>

#define BATCH 4
#define HEADS 16
#define SEQ   2048
#define DIM   64
#define NBH   (BATCH*HEADS)
#define CAP   256
#define NEG_INF __int_as_float(0xff800000)

// per-(row, 64-col block) max scratch: [NBH*SEQ][32]
__device__ float g_tmax[(size_t)NBH * SEQ * 32];

// ================= helpers =================
__device__ __forceinline__ uint32_t smem_u32(const void* p){
    uint32_t a;
    asm("{ .reg .u64 t; cvta.to.shared.u64 t, %1; cvt.u32.u64 %0, t; }" : "=r"(a) : "l"(p));
    return a;
}
#define SWZ(o) ((o) ^ (((o) >> 3) & 0x70))

__device__ __forceinline__ void ldsm_x4(uint32_t* r, uint32_t addr){
    asm volatile("ldmatrix.sync.aligned.m8n8.x4.shared.b16 {%0,%1,%2,%3}, [%4];"
        : "=r"(r[0]), "=r"(r[1]), "=r"(r[2]), "=r"(r[3]) : "r"(addr));
}
__device__ __forceinline__ void mma_bf16(float* c, const uint32_t* a, const uint32_t* b){
    asm volatile("mma.sync.aligned.m16n8k16.row.col.f32.bf16.bf16.f32 "
        "{%0,%1,%2,%3}, {%4,%5,%6,%7}, {%8,%9}, {%0,%1,%2,%3};"
        : "+f"(c[0]), "+f"(c[1]), "+f"(c[2]), "+f"(c[3])
        : "r"(a[0]), "r"(a[1]), "r"(a[2]), "r"(a[3]), "r"(b[0]), "r"(b[1]));
}
__device__ __forceinline__ uint32_t pack_bf2(float a, float b){
    __nv_bfloat16 ha = __float2bfloat16_rn(a), hb = __float2bfloat16_rn(b);
    return (uint32_t)__bfloat16_as_ushort(ha) | ((uint32_t)__bfloat16_as_ushort(hb) << 16);
}

// smem layout: 4 tiles of [128 rows][64 bf16 = 128B] SW128-swizzled
#define SM_QHI 0
#define SM_QLO 16384
#define SM_KHI 32768
#define SM_KLO 49152
#define SM_TOTAL 65536

// ================================================================
// Kernel 1 (HMMA): Xa = (QK^T)*scale*(alpha-1) via bf16 hi/lo split.
// CTA = 128x128, 8 warps (4 m x 2 n), warp tile 32x64, K=64.
// ================================================================
__global__ __launch_bounds__(256) void qk_mma(const float* __restrict__ Q,
                                              const float* __restrict__ Km,
                                              const float* __restrict__ alpha_p,
                                              float* __restrict__ P)
{
    extern __shared__ char smem[];
    const uint32_t sb = smem_u32(smem);
    const int tid = threadIdx.x;

    const int bh = blockIdx.z;
    const int q0 = blockIdx.y * 128;
    const int k0 = blockIdx.x * 128;
    const float* Qb = Q  + (size_t)bh * SEQ * DIM;
    const float* Kb = Km + (size_t)bh * SEQ * DIM;

    // ---- load + hi/lo split-convert Q and K tiles into SW128 smem ----
    for (int i = tid; i < 1024; i += 256){
        const int row = i >> 3, u = i & 7;                     // u: 8-elem unit
        const uint32_t so = SWZ((uint32_t)(row * 128 + u * 16));
        {
            const float* s = Qb + (size_t)(q0 + row) * DIM + u * 8;
            float4 x0 = *(const float4*)s, x1 = *(const float4*)(s + 4);
            float x[8] = {x0.x,x0.y,x0.z,x0.w,x1.x,x1.y,x1.z,x1.w};
            float h[8], lo[8];
            #pragma unroll
            for (int j = 0; j < 8; j++){
                __nv_bfloat16 hb = __float2bfloat16_rn(x[j]);
                h[j] = __bfloat162float(hb); lo[j] = x[j] - h[j];
            }
            *(uint4*)(smem + SM_QHI + so) = make_uint4(pack_bf2(h[0],h[1]), pack_bf2(h[2],h[3]),
                                                       pack_bf2(h[4],h[5]), pack_bf2(h[6],h[7]));
            *(uint4*)(smem + SM_QLO + so) = make_uint4(pack_bf2(lo[0],lo[1]), pack_bf2(lo[2],lo[3]),
                                                       pack_bf2(lo[4],lo[5]), pack_bf2(lo[6],lo[7]));
        }
        {
            const float* s = Kb + (size_t)(k0 + row) * DIM + u * 8;
            float4 x0 = *(const float4*)s, x1 = *(const float4*)(s + 4);
            float x[8] = {x0.x,x0.y,x0.z,x0.w,x1.x,x1.y,x1.z,x1.w};
            float h[8], lo[8];
            #pragma unroll
            for (int j = 0; j < 8; j++){
                __nv_bfloat16 hb = __float2bfloat16_rn(x[j]);
                h[j] = __bfloat162float(hb); lo[j] = x[j] - h[j];
            }
            *(uint4*)(smem + SM_KHI + so) = make_uint4(pack_bf2(h[0],h[1]), pack_bf2(h[2],h[3]),
                                                       pack_bf2(h[4],h[5]), pack_bf2(h[6],h[7]));
            *(uint4*)(smem + SM_KLO + so) = make_uint4(pack_bf2(lo[0],lo[1]), pack_bf2(lo[2],lo[3]),
                                                       pack_bf2(lo[4],lo[5]), pack_bf2(lo[6],lo[7]));
        }
    }
    __syncthreads();

    const int wid = tid >> 5, l = tid & 31;
    const int mw = wid & 3, nw = wid >> 2;
    const int mrow0 = mw * 32, ncol0 = nw * 64;
    const int sub = l >> 3, win = l & 7;

    float acc[2][8][4];
    #pragma unroll
    for (int mt = 0; mt < 2; mt++)
        #pragma unroll
        for (int nt = 0; nt < 8; nt++)
            #pragma unroll
            for (int j = 0; j < 4; j++) acc[mt][nt][j] = 0.0f;

    #pragma unroll 1
    for (int ks = 0; ks < 4; ks++){
        const int kb = ks * 32;                                 // k byte offset
        uint32_t ah[2][4], al[2][4], bhf[8][2], blf[8][2];

        // A fragments: lanes 0-7 rows m..+7 @kb; 8-15 rows +8..15 @kb;
        //              16-23 rows m..+7 @kb+16; 24-31 rows +8..15 @kb+16
        #pragma unroll
        for (int mt = 0; mt < 2; mt++){
            const int row = mrow0 + mt*16 + win + (sub & 1) * 8;
            const int col = kb + (sub >> 1) * 16;
            const uint32_t off = SWZ((uint32_t)(row * 128 + col));
            ldsm_x4(ah[mt], sb + SM_QHI + off);
            ldsm_x4(al[mt], sb + SM_QLO + off);
        }
        // B fragments: x4 covers 2 n-tiles; lanes 0-7 n..+7 @kb; 8-15 n..+7 @kb+16;
        //              16-23 n+8..15 @kb; 24-31 n+8..15 @kb+16
        #pragma unroll
        for (int np = 0; np < 4; np++){
            const int row = ncol0 + np*16 + win + (sub >> 1) * 8;
            const int col = kb + (sub & 1) * 16;
            const uint32_t off = SWZ((uint32_t)(row * 128 + col));
            uint32_t r[4];
            ldsm_x4(r, sb + SM_KHI + off);
            bhf[np*2][0] = r[0]; bhf[np*2][1] = r[1];
            bhf[np*2+1][0] = r[2]; bhf[np*2+1][1] = r[3];
            ldsm_x4(r, sb + SM_KLO + off);
            blf[np*2][0] = r[0]; blf[np*2][1] = r[1];
            blf[np*2+1][0] = r[2]; blf[np*2+1][1] = r[3];
        }
        #pragma unroll
        for (int mt = 0; mt < 2; mt++)
            #pragma unroll
            for (int nt = 0; nt < 8; nt++){
                mma_bf16(acc[mt][nt], ah[mt], bhf[nt]);   // Qh*Kh
                mma_bf16(acc[mt][nt], ah[mt], blf[nt]);   // Qh*Kl
                mma_bf16(acc[mt][nt], al[mt], bhf[nt]);   // Ql*Kh
            }
    }

    // ---- epilogue: scale, store float2, row maxes via quad shuffles ----
    const float sc = (alpha_p[0] - 1.0f) * 0.125f;
    const int g = l >> 2, tq = l & 3;
    const int kb32 = (k0 + ncol0) >> 6;                         // 64-col block idx (0..31)

    #pragma unroll
    for (int mt = 0; mt < 2; mt++){
        float rm0 = NEG_INF, rm1 = NEG_INF;
        const size_t row0 = (size_t)bh * SEQ + q0 + mrow0 + mt*16 + g;
        float* p0 = P + row0 * SEQ + k0 + ncol0 + tq*2;
        #pragma unroll
        for (int nt = 0; nt < 8; nt++){
            float c0 = acc[mt][nt][0]*sc, c1 = acc[mt][nt][1]*sc;
            float c2 = acc[mt][nt][2]*sc, c3 = acc[mt][nt][3]*sc;
            rm0 = fmaxf(rm0, fmaxf(c0, c1));
            rm1 = fmaxf(rm1, fmaxf(c2, c3));
            *(float2*)(p0 + nt*8)           = make_float2(c0, c1);
            *(float2*)(p0 + nt*8 + 8*SEQ)   = make_float2(c2, c3);
        }
        rm0 = fmaxf(rm0, __shfl_xor_sync(0xffffffffu, rm0, 1));
        rm0 = fmaxf(rm0, __shfl_xor_sync(0xffffffffu, rm0, 2));
        rm1 = fmaxf(rm1, __shfl_xor_sync(0xffffffffu, rm1, 1));
        rm1 = fmaxf(rm1, __shfl_xor_sync(0xffffffffu, rm1, 2));
        if (tq == 0){
            g_tmax[row0 * 32 + kb32]       = rm0;
            g_tmax[(row0 + 8) * 32 + kb32] = rm1;
        }
    }
}

// ================================================================
// Kernel 2: warp/row entmax bisection + sparse PV
// ================================================================
template<bool SQ>
__device__ __forceinline__ float pf(float r, float inv){
    return SQ ? r * r : __powf(r, inv);
}
__device__ __forceinline__ float wredmax(float v){
    #pragma unroll
    for (int o = 16; o; o >>= 1) v = fmaxf(v, __shfl_xor_sync(0xffffffffu, v, o));
    return v;
}
__device__ __forceinline__ float wredsum(float v){
    #pragma unroll
    for (int o = 16; o; o >>= 1) v += __shfl_xor_sync(0xffffffffu, v, o);
    return v;
}

template<bool SQ>
__device__ __forceinline__ void row_body(float* __restrict__ prow,
                                         const float* __restrict__ Vb,
                                         float* __restrict__ outrow,
                                         size_t row, float am1, float inv,
                                         float* __restrict__ sval,
                                         int*   __restrict__ sidx,
                                         int l)
{
    float m = g_tmax[row * 32 + l];
    m = wredmax(m);

    float tau        = m - 1.0f;
    const float t_hi = m - powf(1.0f/(float)SEQ, am1);
    float dm         = t_hi - tau;

    const float4* prow4 = (const float4*)prow;
    int A = 0;
    float fl = 0.0f;
    #pragma unroll
    for (int c = 0; c < 16; c++){
        float4 v = prow4[c*32 + l];
        const int jb = (c*32 + l) * 4;
        float vs[4] = {v.x, v.y, v.z, v.w};
        #pragma unroll
        for (int s = 0; s < 4; s++){
            bool act = vs[s] > tau;
            unsigned mk = __ballot_sync(0xffffffffu, act);
            if (act){
                int pos = A + __popc(mk & ((1u << l) - 1u));
                if (pos < CAP){ sval[pos] = vs[s]; sidx[pos] = jb + s; }
                fl += pf<SQ>(vs[s] - tau, inv);
            }
            A += __popc(mk);
        }
    }
    const float f_lo = wredsum(fl) - 1.0f;

    if (A <= CAP){
        float4 z = make_float4(0.f, 0.f, 0.f, 0.f);
        float4* pw = (float4*)prow;
        #pragma unroll
        for (int c = 0; c < 16; c++) pw[c*32 + l] = z;

        #pragma unroll 1
        for (int it = 0; it < 6; it++){
            dm *= 0.5f;
            float tm = tau + dm;
            float fm = 0.f;
            for (int i = l; i < A; i += 32)
                fm += pf<SQ>(fmaxf(sval[i] - tm, 0.f), inv);
            fm = wredsum(fm) - 1.0f;
            if (fm * f_lo >= 0.0f) tau = tm;
        }

        int A2 = 0;
        for (int base = 0; base < A; base += 32){
            int i = base + l;
            float vv = (i < A) ? sval[i] : NEG_INF;
            int   ii = (i < A) ? sidx[i] : 0;
            bool keep = vv > tau;
            unsigned mk = __ballot_sync(0xffffffffu, keep);
            if (keep){
                int pos = A2 + __popc(mk & ((1u << l) - 1u));
                sval[pos] = vv; sidx[pos] = ii;
            }
            A2 += __popc(mk);
        }
        A = A2;
        __syncwarp();

        #pragma unroll 1
        for (int it = 0; it < 21; it++){
            dm *= 0.5f;
            float tm = tau + dm;
            float fm = 0.f;
            for (int i = l; i < A; i += 32)
                fm += pf<SQ>(fmaxf(sval[i] - tm, 0.f), inv);
            fm = wredsum(fm) - 1.0f;
            if (fm * f_lo >= 0.0f) tau = tm;
        }

        float ss = 0.f;
        for (int i = l; i < A; i += 32)
            ss += pf<SQ>(fmaxf(sval[i] - tau, 0.f), inv);
        const float isum = 1.0f / wredsum(ss);

        __syncwarp();
        for (int i = l; i < A; i += 32){
            float r = sval[i] - tau;
            if (r > 0.0f) prow[sidx[i]] = pf<SQ>(r, inv) * isum;
        }

        float ax = 0.f, ay = 0.f;
        #pragma unroll 2
        for (int i = 0; i < A; i++){
            float r = sval[i] - tau;
            if (r > 0.0f){
                float p = pf<SQ>(r, inv) * isum;
                float2 vv = *(const float2*)(Vb + (size_t)sidx[i]*DIM + 2*l);
                ax += p * vv.x; ay += p * vv.y;
            }
        }
        *(float2*)(outrow + 2*l) = make_float2(ax, ay);
    } else {
        for (int it = 0; it < 27; it++){
            dm *= 0.5f;
            float tm = tau + dm;
            float fm = 0.f;
            for (int j = l; j < SEQ; j += 32)
                fm += pf<SQ>(fmaxf(prow[j] - tm, 0.f), inv);
            fm = wredsum(fm) - 1.0f;
            if (fm * f_lo >= 0.0f) tau = tm;
        }
        float ss = 0.f;
        for (int j = l; j < SEQ; j += 32)
            ss += pf<SQ>(fmaxf(prow[j] - tau, 0.f), inv);
        float isum = 1.0f / wredsum(ss);

        for (int j = l; j < SEQ; j += 32){
            float r = fmaxf(prow[j] - tau, 0.f);
            prow[j] = pf<SQ>(r, inv) * isum;
        }
        __syncwarp();
        float ax = 0.f, ay = 0.f;
        for (int k = 0; k < SEQ; k++){
            float p = prow[k];
            if (p > 0.0f){
                float2 vv = *(const float2*)(Vb + (size_t)k*DIM + 2*l);
                ax += p * vv.x; ay += p * vv.y;
            }
        }
        *(float2*)(outrow + 2*l) = make_float2(ax, ay);
    }
}

__global__ __launch_bounds__(256, 6) void entmax_pv_warp(const float* __restrict__ V,
        const float* __restrict__ alpha_p, float* __restrict__ out, float* __restrict__ P)
{
    __shared__ float sval[8][CAP];
    __shared__ int   sidx[8][CAP];

    const int w   = threadIdx.x >> 5;
    const int l   = threadIdx.x & 31;
    const size_t row = (size_t)blockIdx.x * 8 + w;
    const int bh  = (int)(row >> 11);

    float* prow = P + row * SEQ;
    const float* Vb = V + (size_t)bh * SEQ * DIM;
    float* outrow = out + row * DIM;

    const float am1 = alpha_p[0] - 1.0f;
    const float inv = 1.0f / am1;
    const bool  sq  = fabsf(inv - 2.0f) < 1e-6f;

    if (sq) row_body<true >(prow, Vb, outrow, row, am1, inv, sval[w], sidx[w], l);
    else    row_body<false>(prow, Vb, outrow, row, am1, inv, sval[w], sidx[w], l);
}

// ================================================================
extern "C" void kernel_launch(void* const* d_in, const int* in_sizes, int n_in,
                              void* d_out, int out_size)
{
    const float* Q     = (const float*)d_in[0];
    const float* K     = (const float*)d_in[1];
    const float* V     = (const float*)d_in[2];
    const float* alpha = (const float*)d_in[3];

    float* out = (float*)d_out;                              // [B,H,S,D]
    float* P   = out + (size_t)NBH * SEQ * DIM;              // [B,H,S,S]

    cudaFuncSetAttribute(qk_mma, cudaFuncAttributeMaxDynamicSharedMemorySize, SM_TOTAL);

    dim3 g1(SEQ/128, SEQ/128, NBH);
    qk_mma<<<g1, 256, SM_TOTAL>>>(Q, K, alpha, P);

    entmax_pv_warp<<<(NBH * SEQ) / 8, 256>>>(V, alpha, out, P);
}

// round 6
// speedup vs baseline: 1.5748x; 1.5748x over previous
#include <cuda_runtime.h>
#include <cuda_bf16.h>
#include <cstdint>
#include <cstddef>

#define BATCH 4
#define HEADS 16
#define SEQ   2048
#define DIM   64
#define NBH   (BATCH*HEADS)
#define CAP   512
#define NEG_INF __int_as_float(0xff800000)

// per-(row, 64-col block) max scratch: [NBH*SEQ][32]
__device__ float g_tmax[(size_t)NBH * SEQ * 32];

// ================= helpers =================
__device__ __forceinline__ uint32_t smem_u32(const void* p){
    uint32_t a;
    asm("{ .reg .u64 t; cvta.to.shared.u64 t, %1; cvt.u32.u64 %0, t; }" : "=r"(a) : "l"(p));
    return a;
}
#define SWZ(o) ((o) ^ (((o) >> 3) & 0x70))

__device__ __forceinline__ void ldsm_x4(uint32_t* r, uint32_t addr){
    asm volatile("ldmatrix.sync.aligned.m8n8.x4.shared.b16 {%0,%1,%2,%3}, [%4];"
        : "=r"(r[0]), "=r"(r[1]), "=r"(r[2]), "=r"(r[3]) : "r"(addr));
}
__device__ __forceinline__ void mma_bf16(float* c, const uint32_t* a, const uint32_t* b){
    asm volatile("mma.sync.aligned.m16n8k16.row.col.f32.bf16.bf16.f32 "
        "{%0,%1,%2,%3}, {%4,%5,%6,%7}, {%8,%9}, {%0,%1,%2,%3};"
        : "+f"(c[0]), "+f"(c[1]), "+f"(c[2]), "+f"(c[3])
        : "r"(a[0]), "r"(a[1]), "r"(a[2]), "r"(a[3]), "r"(b[0]), "r"(b[1]));
}
__device__ __forceinline__ uint32_t pack_bf2(float a, float b){
    __nv_bfloat16 ha = __float2bfloat16_rn(a), hb = __float2bfloat16_rn(b);
    return (uint32_t)__bfloat16_as_ushort(ha) | ((uint32_t)__bfloat16_as_ushort(hb) << 16);
}

// smem layout: 4 tiles of [128 rows][64 bf16 = 128B] SW128-swizzled
#define SM_QHI 0
#define SM_QLO 16384
#define SM_KHI 32768
#define SM_KLO 49152
#define SM_TOTAL 65536

// ================================================================
// Kernel 1 (HMMA): Xa = (QK^T)*scale*(alpha-1) via bf16 hi/lo split.
// CTA = 128x128, 8 warps (4 m x 2 n), warp tile 32x64, K=64.
// ================================================================
__global__ __launch_bounds__(256) void qk_mma(const float* __restrict__ Q,
                                              const float* __restrict__ Km,
                                              const float* __restrict__ alpha_p,
                                              float* __restrict__ P)
{
    extern __shared__ char smem[];
    const uint32_t sb = smem_u32(smem);
    const int tid = threadIdx.x;

    const int bh = blockIdx.z;
    const int q0 = blockIdx.y * 128;
    const int k0 = blockIdx.x * 128;
    const float* Qb = Q  + (size_t)bh * SEQ * DIM;
    const float* Kb = Km + (size_t)bh * SEQ * DIM;

    // ---- load + hi/lo split-convert Q and K tiles into SW128 smem ----
    for (int i = tid; i < 1024; i += 256){
        const int row = i >> 3, u = i & 7;
        const uint32_t so = SWZ((uint32_t)(row * 128 + u * 16));
        {
            const float* s = Qb + (size_t)(q0 + row) * DIM + u * 8;
            float4 x0 = *(const float4*)s, x1 = *(const float4*)(s + 4);
            float x[8] = {x0.x,x0.y,x0.z,x0.w,x1.x,x1.y,x1.z,x1.w};
            float h[8], lo[8];
            #pragma unroll
            for (int j = 0; j < 8; j++){
                __nv_bfloat16 hb = __float2bfloat16_rn(x[j]);
                h[j] = __bfloat162float(hb); lo[j] = x[j] - h[j];
            }
            *(uint4*)(smem + SM_QHI + so) = make_uint4(pack_bf2(h[0],h[1]), pack_bf2(h[2],h[3]),
                                                       pack_bf2(h[4],h[5]), pack_bf2(h[6],h[7]));
            *(uint4*)(smem + SM_QLO + so) = make_uint4(pack_bf2(lo[0],lo[1]), pack_bf2(lo[2],lo[3]),
                                                       pack_bf2(lo[4],lo[5]), pack_bf2(lo[6],lo[7]));
        }
        {
            const float* s = Kb + (size_t)(k0 + row) * DIM + u * 8;
            float4 x0 = *(const float4*)s, x1 = *(const float4*)(s + 4);
            float x[8] = {x0.x,x0.y,x0.z,x0.w,x1.x,x1.y,x1.z,x1.w};
            float h[8], lo[8];
            #pragma unroll
            for (int j = 0; j < 8; j++){
                __nv_bfloat16 hb = __float2bfloat16_rn(x[j]);
                h[j] = __bfloat162float(hb); lo[j] = x[j] - h[j];
            }
            *(uint4*)(smem + SM_KHI + so) = make_uint4(pack_bf2(h[0],h[1]), pack_bf2(h[2],h[3]),
                                                       pack_bf2(h[4],h[5]), pack_bf2(h[6],h[7]));
            *(uint4*)(smem + SM_KLO + so) = make_uint4(pack_bf2(lo[0],lo[1]), pack_bf2(lo[2],lo[3]),
                                                       pack_bf2(lo[4],lo[5]), pack_bf2(lo[6],lo[7]));
        }
    }
    __syncthreads();

    const int wid = tid >> 5, l = tid & 31;
    const int mw = wid & 3, nw = wid >> 2;
    const int mrow0 = mw * 32, ncol0 = nw * 64;
    const int sub = l >> 3, win = l & 7;

    float acc[2][8][4];
    #pragma unroll
    for (int mt = 0; mt < 2; mt++)
        #pragma unroll
        for (int nt = 0; nt < 8; nt++)
            #pragma unroll
            for (int j = 0; j < 4; j++) acc[mt][nt][j] = 0.0f;

    #pragma unroll 1
    for (int ks = 0; ks < 4; ks++){
        const int kb = ks * 32;
        uint32_t ah[2][4], al[2][4], bhf[8][2], blf[8][2];

        #pragma unroll
        for (int mt = 0; mt < 2; mt++){
            const int row = mrow0 + mt*16 + win + (sub & 1) * 8;
            const int col = kb + (sub >> 1) * 16;
            const uint32_t off = SWZ((uint32_t)(row * 128 + col));
            ldsm_x4(ah[mt], sb + SM_QHI + off);
            ldsm_x4(al[mt], sb + SM_QLO + off);
        }
        #pragma unroll
        for (int np = 0; np < 4; np++){
            const int row = ncol0 + np*16 + win + (sub >> 1) * 8;
            const int col = kb + (sub & 1) * 16;
            const uint32_t off = SWZ((uint32_t)(row * 128 + col));
            uint32_t r[4];
            ldsm_x4(r, sb + SM_KHI + off);
            bhf[np*2][0] = r[0]; bhf[np*2][1] = r[1];
            bhf[np*2+1][0] = r[2]; bhf[np*2+1][1] = r[3];
            ldsm_x4(r, sb + SM_KLO + off);
            blf[np*2][0] = r[0]; blf[np*2][1] = r[1];
            blf[np*2+1][0] = r[2]; blf[np*2+1][1] = r[3];
        }
        #pragma unroll
        for (int mt = 0; mt < 2; mt++)
            #pragma unroll
            for (int nt = 0; nt < 8; nt++){
                mma_bf16(acc[mt][nt], ah[mt], bhf[nt]);
                mma_bf16(acc[mt][nt], ah[mt], blf[nt]);
                mma_bf16(acc[mt][nt], al[mt], bhf[nt]);
            }
    }

    // ---- epilogue: scale, store float2, row maxes via quad shuffles ----
    const float sc = (alpha_p[0] - 1.0f) * 0.125f;
    const int g = l >> 2, tq = l & 3;
    const int kb32 = (k0 + ncol0) >> 6;

    #pragma unroll
    for (int mt = 0; mt < 2; mt++){
        float rm0 = NEG_INF, rm1 = NEG_INF;
        const size_t row0 = (size_t)bh * SEQ + q0 + mrow0 + mt*16 + g;
        float* p0 = P + row0 * SEQ + k0 + ncol0 + tq*2;
        #pragma unroll
        for (int nt = 0; nt < 8; nt++){
            float c0 = acc[mt][nt][0]*sc, c1 = acc[mt][nt][1]*sc;
            float c2 = acc[mt][nt][2]*sc, c3 = acc[mt][nt][3]*sc;
            rm0 = fmaxf(rm0, fmaxf(c0, c1));
            rm1 = fmaxf(rm1, fmaxf(c2, c3));
            *(float2*)(p0 + nt*8)           = make_float2(c0, c1);
            *(float2*)(p0 + nt*8 + 8*SEQ)   = make_float2(c2, c3);
        }
        rm0 = fmaxf(rm0, __shfl_xor_sync(0xffffffffu, rm0, 1));
        rm0 = fmaxf(rm0, __shfl_xor_sync(0xffffffffu, rm0, 2));
        rm1 = fmaxf(rm1, __shfl_xor_sync(0xffffffffu, rm1, 1));
        rm1 = fmaxf(rm1, __shfl_xor_sync(0xffffffffu, rm1, 2));
        if (tq == 0){
            g_tmax[row0 * 32 + kb32]       = rm0;
            g_tmax[(row0 + 8) * 32 + kb32] = rm1;
        }
    }
}

// ================================================================
// Kernel 2: warp/row entmax bisection + sparse PV (CAP=512, occ 6)
// ================================================================
template<bool SQ>
__device__ __forceinline__ float pf(float r, float inv){
    return SQ ? r * r : __powf(r, inv);
}
__device__ __forceinline__ float wredmax(float v){
    #pragma unroll
    for (int o = 16; o; o >>= 1) v = fmaxf(v, __shfl_xor_sync(0xffffffffu, v, o));
    return v;
}
__device__ __forceinline__ float wredsum(float v){
    #pragma unroll
    for (int o = 16; o; o >>= 1) v += __shfl_xor_sync(0xffffffffu, v, o);
    return v;
}

template<bool SQ>
__device__ __forceinline__ void row_body(float* __restrict__ prow,
                                         const float* __restrict__ Vb,
                                         float* __restrict__ outrow,
                                         size_t row, float am1, float inv,
                                         float* __restrict__ sval,
                                         int*   __restrict__ sidx,
                                         int l)
{
    float m = g_tmax[row * 32 + l];
    m = wredmax(m);

    float tau        = m - 1.0f;
    const float t_hi = m - powf(1.0f/(float)SEQ, am1);
    float dm         = t_hi - tau;

    const float4* prow4 = (const float4*)prow;
    int A = 0;
    float fl = 0.0f;
    #pragma unroll
    for (int c = 0; c < 16; c++){
        float4 v = prow4[c*32 + l];
        const int jb = (c*32 + l) * 4;
        float vs[4] = {v.x, v.y, v.z, v.w};
        #pragma unroll
        for (int s = 0; s < 4; s++){
            bool act = vs[s] > tau;
            unsigned mk = __ballot_sync(0xffffffffu, act);
            if (act){
                int pos = A + __popc(mk & ((1u << l) - 1u));
                if (pos < CAP){ sval[pos] = vs[s]; sidx[pos] = jb + s; }
                fl += pf<SQ>(vs[s] - tau, inv);
            }
            A += __popc(mk);
        }
    }
    const float f_lo = wredsum(fl) - 1.0f;

    if (A <= CAP){
        float4 z = make_float4(0.f, 0.f, 0.f, 0.f);
        float4* pw = (float4*)prow;
        #pragma unroll
        for (int c = 0; c < 16; c++) pw[c*32 + l] = z;

        #pragma unroll 1
        for (int it = 0; it < 6; it++){
            dm *= 0.5f;
            float tm = tau + dm;
            float fm = 0.f;
            for (int i = l; i < A; i += 32)
                fm += pf<SQ>(fmaxf(sval[i] - tm, 0.f), inv);
            fm = wredsum(fm) - 1.0f;
            if (fm * f_lo >= 0.0f) tau = tm;
        }

        int A2 = 0;
        for (int base = 0; base < A; base += 32){
            int i = base + l;
            float vv = (i < A) ? sval[i] : NEG_INF;
            int   ii = (i < A) ? sidx[i] : 0;
            bool keep = vv > tau;
            unsigned mk = __ballot_sync(0xffffffffu, keep);
            if (keep){
                int pos = A2 + __popc(mk & ((1u << l) - 1u));
                sval[pos] = vv; sidx[pos] = ii;
            }
            A2 += __popc(mk);
        }
        A = A2;
        __syncwarp();

        #pragma unroll 1
        for (int it = 0; it < 21; it++){
            dm *= 0.5f;
            float tm = tau + dm;
            float fm = 0.f;
            for (int i = l; i < A; i += 32)
                fm += pf<SQ>(fmaxf(sval[i] - tm, 0.f), inv);
            fm = wredsum(fm) - 1.0f;
            if (fm * f_lo >= 0.0f) tau = tm;
        }

        float ss = 0.f;
        for (int i = l; i < A; i += 32)
            ss += pf<SQ>(fmaxf(sval[i] - tau, 0.f), inv);
        const float isum = 1.0f / wredsum(ss);

        __syncwarp();
        for (int i = l; i < A; i += 32){
            float r = sval[i] - tau;
            if (r > 0.0f) prow[sidx[i]] = pf<SQ>(r, inv) * isum;
        }

        float ax = 0.f, ay = 0.f;
        #pragma unroll 2
        for (int i = 0; i < A; i++){
            float r = sval[i] - tau;
            if (r > 0.0f){
                float p = pf<SQ>(r, inv) * isum;
                float2 vv = *(const float2*)(Vb + (size_t)sidx[i]*DIM + 2*l);
                ax += p * vv.x; ay += p * vv.y;
            }
        }
        *(float2*)(outrow + 2*l) = make_float2(ax, ay);
    } else {
        for (int it = 0; it < 27; it++){
            dm *= 0.5f;
            float tm = tau + dm;
            float fm = 0.f;
            for (int j = l; j < SEQ; j += 32)
                fm += pf<SQ>(fmaxf(prow[j] - tm, 0.f), inv);
            fm = wredsum(fm) - 1.0f;
            if (fm * f_lo >= 0.0f) tau = tm;
        }
        float ss = 0.f;
        for (int j = l; j < SEQ; j += 32)
            ss += pf<SQ>(fmaxf(prow[j] - tau, 0.f), inv);
        float isum = 1.0f / wredsum(ss);

        for (int j = l; j < SEQ; j += 32){
            float r = fmaxf(prow[j] - tau, 0.f);
            prow[j] = pf<SQ>(r, inv) * isum;
        }
        __syncwarp();
        float ax = 0.f, ay = 0.f;
        for (int k = 0; k < SEQ; k++){
            float p = prow[k];
            if (p > 0.0f){
                float2 vv = *(const float2*)(Vb + (size_t)k*DIM + 2*l);
                ax += p * vv.x; ay += p * vv.y;
            }
        }
        *(float2*)(outrow + 2*l) = make_float2(ax, ay);
    }
}

__global__ __launch_bounds__(256, 6) void entmax_pv_warp(const float* __restrict__ V,
        const float* __restrict__ alpha_p, float* __restrict__ out, float* __restrict__ P)
{
    __shared__ float sval[8][CAP];
    __shared__ int   sidx[8][CAP];

    const int w   = threadIdx.x >> 5;
    const int l   = threadIdx.x & 31;
    const size_t row = (size_t)blockIdx.x * 8 + w;
    const int bh  = (int)(row >> 11);

    float* prow = P + row * SEQ;
    const float* Vb = V + (size_t)bh * SEQ * DIM;
    float* outrow = out + row * DIM;

    const float am1 = alpha_p[0] - 1.0f;
    const float inv = 1.0f / am1;
    const bool  sq  = fabsf(inv - 2.0f) < 1e-6f;

    if (sq) row_body<true >(prow, Vb, outrow, row, am1, inv, sval[w], sidx[w], l);
    else    row_body<false>(prow, Vb, outrow, row, am1, inv, sval[w], sidx[w], l);
}

// ================================================================
extern "C" void kernel_launch(void* const* d_in, const int* in_sizes, int n_in,
                              void* d_out, int out_size)
{
    const float* Q     = (const float*)d_in[0];
    const float* K     = (const float*)d_in[1];
    const float* V     = (const float*)d_in[2];
    const float* alpha = (const float*)d_in[3];

    float* out = (float*)d_out;                              // [B,H,S,D]
    float* P   = out + (size_t)NBH * SEQ * DIM;              // [B,H,S,S]

    cudaFuncSetAttribute(qk_mma, cudaFuncAttributeMaxDynamicSharedMemorySize, SM_TOTAL);

    dim3 g1(SEQ/128, SEQ/128, NBH);
    qk_mma<<<g1, 256, SM_TOTAL>>>(Q, K, alpha, P);

    entmax_pv_warp<<<(NBH * SEQ) / 8, 256>>>(V, alpha, out, P);
}

// round 7
// speedup vs baseline: 1.7207x; 1.0926x over previous
#include <cuda_runtime.h>
#include <cuda_bf16.h>
#include <cstdint>
#include <cstddef>

#define BATCH 4
#define HEADS 16
#define SEQ   2048
#define DIM   64
#define NBH   (BATCH*HEADS)
#define CAP   512
#define NEG_INF __int_as_float(0xff800000)

// per-(row, 64-col block) max scratch: [NBH*SEQ][32]
__device__ float g_tmax[(size_t)NBH * SEQ * 32];
// pre-split bf16 hi/lo copies of Q and K (16MB each)
__device__ __nv_bfloat16 g_qhi[(size_t)NBH * SEQ * DIM];
__device__ __nv_bfloat16 g_qlo[(size_t)NBH * SEQ * DIM];
__device__ __nv_bfloat16 g_khi[(size_t)NBH * SEQ * DIM];
__device__ __nv_bfloat16 g_klo[(size_t)NBH * SEQ * DIM];

// ================= helpers =================
__device__ __forceinline__ uint32_t smem_u32(const void* p){
    uint32_t a;
    asm("{ .reg .u64 t; cvta.to.shared.u64 t, %1; cvt.u32.u64 %0, t; }" : "=r"(a) : "l"(p));
    return a;
}
#define SWZ(o) ((o) ^ (((o) >> 3) & 0x70))

__device__ __forceinline__ void ldsm_x4(uint32_t* r, uint32_t addr){
    asm volatile("ldmatrix.sync.aligned.m8n8.x4.shared.b16 {%0,%1,%2,%3}, [%4];"
        : "=r"(r[0]), "=r"(r[1]), "=r"(r[2]), "=r"(r[3]) : "r"(addr));
}
__device__ __forceinline__ void mma_bf16(float* c, const uint32_t* a, const uint32_t* b){
    asm volatile("mma.sync.aligned.m16n8k16.row.col.f32.bf16.bf16.f32 "
        "{%0,%1,%2,%3}, {%4,%5,%6,%7}, {%8,%9}, {%0,%1,%2,%3};"
        : "+f"(c[0]), "+f"(c[1]), "+f"(c[2]), "+f"(c[3])
        : "r"(a[0]), "r"(a[1]), "r"(a[2]), "r"(a[3]), "r"(b[0]), "r"(b[1]));
}

// ================================================================
// Kernel 0: split Q,K fp32 -> bf16 hi + bf16 lo (done ONCE, not 16x)
// ================================================================
__global__ __launch_bounds__(256) void split_kernel(const float* __restrict__ Q,
                                                    const float* __restrict__ Km)
{
    size_t t = (size_t)blockIdx.x * 256 + threadIdx.x;
    const size_t PER = (size_t)NBH * SEQ * DIM / 8;
    const float* src;
    __nv_bfloat16 *hid, *lod;
    if (t < PER){ src = Q;  hid = g_qhi; lod = g_qlo; }
    else        { t -= PER; src = Km; hid = g_khi; lod = g_klo; }
    const size_t e = t * 8;
    float4 a = *(const float4*)(src + e);
    float4 b = *(const float4*)(src + e + 4);
    float x[8] = {a.x,a.y,a.z,a.w,b.x,b.y,b.z,b.w};
    uint32_t hp[4], lp[4];
    #pragma unroll
    for (int j = 0; j < 4; j++){
        __nv_bfloat162 h2 = __float22bfloat162_rn(make_float2(x[2*j], x[2*j+1]));
        hp[j] = *(uint32_t*)&h2;
        float l0 = x[2*j]   - __low2float(h2);
        float l1 = x[2*j+1] - __high2float(h2);
        __nv_bfloat162 l2 = __float22bfloat162_rn(make_float2(l0, l1));
        lp[j] = *(uint32_t*)&l2;
    }
    *(uint4*)(hid + e) = make_uint4(hp[0], hp[1], hp[2], hp[3]);
    *(uint4*)(lod + e) = make_uint4(lp[0], lp[1], lp[2], lp[3]);
}

// smem layout: 4 tiles of [128 rows][64 bf16 = 128B] SW128-swizzled
#define SM_QHI 0
#define SM_QLO 16384
#define SM_KHI 32768
#define SM_KLO 49152
#define SM_TOTAL 65536

// ================================================================
// Kernel 1 (HMMA): Xa = (QK^T)*scale*(alpha-1), pre-split bf16 inputs.
// CTA = 128x128, 8 warps (4 m x 2 n), warp tile 32x64, K=64.
// ================================================================
__global__ __launch_bounds__(256) void qk_mma(const float* __restrict__ alpha_p,
                                              float* __restrict__ P)
{
    extern __shared__ char smem[];
    const uint32_t sb = smem_u32(smem);
    const int tid = threadIdx.x;

    const int bh = blockIdx.z;
    const int q0 = blockIdx.y * 128;
    const int k0 = blockIdx.x * 128;

    // ---- prologue: pure copy of pre-split bf16 tiles into SW128 smem ----
    {
        const size_t bq = ((size_t)bh * SEQ + q0) * DIM;
        const size_t bk = ((size_t)bh * SEQ + k0) * DIM;
        const __nv_bfloat16* srcs[4] = {g_qhi + bq, g_qlo + bq, g_khi + bk, g_klo + bk};
        #pragma unroll
        for (int m = 0; m < 4; m++){
            const __nv_bfloat16* s = srcs[m];
            char* dst = smem + m * 16384;
            #pragma unroll
            for (int i = tid; i < 1024; i += 256){
                int row = i >> 3, u = i & 7;
                uint4 v = *(const uint4*)(s + row * 64 + u * 8);
                *(uint4*)(dst + SWZ((uint32_t)(row * 128 + u * 16))) = v;
            }
        }
    }
    __syncthreads();

    const int wid = tid >> 5, l = tid & 31;
    const int mw = wid & 3, nw = wid >> 2;
    const int mrow0 = mw * 32, ncol0 = nw * 64;
    const int sub = l >> 3, win = l & 7;

    float acc[2][8][4];
    #pragma unroll
    for (int mt = 0; mt < 2; mt++)
        #pragma unroll
        for (int nt = 0; nt < 8; nt++)
            #pragma unroll
            for (int j = 0; j < 4; j++) acc[mt][nt][j] = 0.0f;

    #pragma unroll 1
    for (int ks = 0; ks < 4; ks++){
        const int kb = ks * 32;
        uint32_t ah[2][4], al[2][4], bhf[8][2], blf[8][2];

        #pragma unroll
        for (int mt = 0; mt < 2; mt++){
            const int row = mrow0 + mt*16 + win + (sub & 1) * 8;
            const int col = kb + (sub >> 1) * 16;
            const uint32_t off = SWZ((uint32_t)(row * 128 + col));
            ldsm_x4(ah[mt], sb + SM_QHI + off);
            ldsm_x4(al[mt], sb + SM_QLO + off);
        }
        #pragma unroll
        for (int np = 0; np < 4; np++){
            const int row = ncol0 + np*16 + win + (sub >> 1) * 8;
            const int col = kb + (sub & 1) * 16;
            const uint32_t off = SWZ((uint32_t)(row * 128 + col));
            uint32_t r[4];
            ldsm_x4(r, sb + SM_KHI + off);
            bhf[np*2][0] = r[0]; bhf[np*2][1] = r[1];
            bhf[np*2+1][0] = r[2]; bhf[np*2+1][1] = r[3];
            ldsm_x4(r, sb + SM_KLO + off);
            blf[np*2][0] = r[0]; blf[np*2][1] = r[1];
            blf[np*2+1][0] = r[2]; blf[np*2+1][1] = r[3];
        }
        #pragma unroll
        for (int mt = 0; mt < 2; mt++)
            #pragma unroll
            for (int nt = 0; nt < 8; nt++){
                mma_bf16(acc[mt][nt], ah[mt], bhf[nt]);
                mma_bf16(acc[mt][nt], ah[mt], blf[nt]);
                mma_bf16(acc[mt][nt], al[mt], bhf[nt]);
            }
    }

    // ---- epilogue: scale, store float2, row maxes via quad shuffles ----
    const float sc = (alpha_p[0] - 1.0f) * 0.125f;
    const int g = l >> 2, tq = l & 3;
    const int kb32 = (k0 + ncol0) >> 6;

    #pragma unroll
    for (int mt = 0; mt < 2; mt++){
        float rm0 = NEG_INF, rm1 = NEG_INF;
        const size_t row0 = (size_t)bh * SEQ + q0 + mrow0 + mt*16 + g;
        float* p0 = P + row0 * SEQ + k0 + ncol0 + tq*2;
        #pragma unroll
        for (int nt = 0; nt < 8; nt++){
            float c0 = acc[mt][nt][0]*sc, c1 = acc[mt][nt][1]*sc;
            float c2 = acc[mt][nt][2]*sc, c3 = acc[mt][nt][3]*sc;
            rm0 = fmaxf(rm0, fmaxf(c0, c1));
            rm1 = fmaxf(rm1, fmaxf(c2, c3));
            *(float2*)(p0 + nt*8)           = make_float2(c0, c1);
            *(float2*)(p0 + nt*8 + 8*SEQ)   = make_float2(c2, c3);
        }
        rm0 = fmaxf(rm0, __shfl_xor_sync(0xffffffffu, rm0, 1));
        rm0 = fmaxf(rm0, __shfl_xor_sync(0xffffffffu, rm0, 2));
        rm1 = fmaxf(rm1, __shfl_xor_sync(0xffffffffu, rm1, 1));
        rm1 = fmaxf(rm1, __shfl_xor_sync(0xffffffffu, rm1, 2));
        if (tq == 0){
            g_tmax[row0 * 32 + kb32]       = rm0;
            g_tmax[(row0 + 8) * 32 + kb32] = rm1;
        }
    }
}

// ================================================================
// Kernel 2: warp/row entmax bisection + sparse PV
// ================================================================
template<bool SQ>
__device__ __forceinline__ float pf(float r, float inv){
    return SQ ? r * r : __powf(r, inv);
}
__device__ __forceinline__ float wredmax(float v){
    #pragma unroll
    for (int o = 16; o; o >>= 1) v = fmaxf(v, __shfl_xor_sync(0xffffffffu, v, o));
    return v;
}
__device__ __forceinline__ float wredsum(float v){
    #pragma unroll
    for (int o = 16; o; o >>= 1) v += __shfl_xor_sync(0xffffffffu, v, o);
    return v;
}

template<bool SQ>
__device__ __forceinline__ void row_body(float* __restrict__ prow,
                                         const float* __restrict__ Vb,
                                         float* __restrict__ outrow,
                                         size_t row, float am1, float inv,
                                         float* __restrict__ sval,
                                         int*   __restrict__ sidx,
                                         int l)
{
    float m = g_tmax[row * 32 + l];
    m = wredmax(m);

    float tau        = m - 1.0f;
    const float t_hi = m - powf(1.0f/(float)SEQ, am1);
    float dm         = t_hi - tau;

    const float4* prow4 = (const float4*)prow;
    int A = 0;
    float fl = 0.0f;
    #pragma unroll
    for (int c = 0; c < 16; c++){
        float4 v = prow4[c*32 + l];
        const int jb = (c*32 + l) * 4;
        float vs[4] = {v.x, v.y, v.z, v.w};
        #pragma unroll
        for (int s = 0; s < 4; s++){
            bool act = vs[s] > tau;
            unsigned mk = __ballot_sync(0xffffffffu, act);
            if (act){
                int pos = A + __popc(mk & ((1u << l) - 1u));
                if (pos < CAP){ sval[pos] = vs[s]; sidx[pos] = jb + s; }
                fl += pf<SQ>(vs[s] - tau, inv);
            }
            A += __popc(mk);
        }
    }
    const float f_lo = wredsum(fl) - 1.0f;

    if (A <= CAP){
        float4 z = make_float4(0.f, 0.f, 0.f, 0.f);
        float4* pw = (float4*)prow;
        #pragma unroll
        for (int c = 0; c < 16; c++) pw[c*32 + l] = z;

        // ---- phase 1: 6 iters over full candidate list (smem) ----
        #pragma unroll 1
        for (int it = 0; it < 6; it++){
            dm *= 0.5f;
            float tm = tau + dm;
            float fm = 0.f;
            for (int i = l; i < A; i += 32)
                fm += pf<SQ>(fmaxf(sval[i] - tm, 0.f), inv);
            fm = wredsum(fm) - 1.0f;
            if (fm * f_lo >= 0.0f) tau = tm;
        }

        // ---- recompact (tau monotone; dropped elems stay p=0 forever) ----
        int A2 = 0;
        for (int base = 0; base < A; base += 32){
            int i = base + l;
            float vv = (i < A) ? sval[i] : NEG_INF;
            int   ii = (i < A) ? sidx[i] : 0;
            bool keep = vv > tau;
            unsigned mk = __ballot_sync(0xffffffffu, keep);
            if (keep){
                int pos = A2 + __popc(mk & ((1u << l) - 1u));
                sval[pos] = vv; sidx[pos] = ii;
            }
            A2 += __popc(mk);
        }
        A = A2;
        __syncwarp();

        if (A <= 64){
            // ---- phase 2 from registers (common case, A~30-40) ----
            float w0 = (l      < A) ? sval[l]      : NEG_INF;
            float w1 = (l + 32 < A) ? sval[l + 32] : NEG_INF;
            int   j0 = (l      < A) ? sidx[l]      : 0;
            int   j1 = (l + 32 < A) ? sidx[l + 32] : 0;

            #pragma unroll 1
            for (int it = 0; it < 21; it++){
                dm *= 0.5f;
                float tm = tau + dm;
                float a0 = fmaxf(w0 - tm, 0.f), a1 = fmaxf(w1 - tm, 0.f);
                float fm = wredsum(pf<SQ>(a0, inv) + pf<SQ>(a1, inv)) - 1.0f;
                if (fm * f_lo >= 0.0f) tau = tm;
            }
            float a0 = fmaxf(w0 - tau, 0.f), a1 = fmaxf(w1 - tau, 0.f);
            float p0 = pf<SQ>(a0, inv), p1 = pf<SQ>(a1, inv);
            const float isum = 1.0f / wredsum(p0 + p1);
            p0 *= isum; p1 *= isum;

            __syncwarp();
            if (p0 > 0.0f) prow[j0] = p0;
            if (p1 > 0.0f) prow[j1] = p1;
            // prestore p for branch-free PV
            sval[l]      = p0;
            sval[l + 32] = p1;
            __syncwarp();

            float ax = 0.f, ay = 0.f;
            #pragma unroll 4
            for (int i = 0; i < A; i++){
                float p = sval[i];
                float2 vv = *(const float2*)(Vb + (size_t)sidx[i]*DIM + 2*l);
                ax += p * vv.x; ay += p * vv.y;
            }
            *(float2*)(outrow + 2*l) = make_float2(ax, ay);
        } else {
            // ---- phase 2 general (smem) ----
            #pragma unroll 1
            for (int it = 0; it < 21; it++){
                dm *= 0.5f;
                float tm = tau + dm;
                float fm = 0.f;
                for (int i = l; i < A; i += 32)
                    fm += pf<SQ>(fmaxf(sval[i] - tm, 0.f), inv);
                fm = wredsum(fm) - 1.0f;
                if (fm * f_lo >= 0.0f) tau = tm;
            }
            float ss = 0.f;
            for (int i = l; i < A; i += 32)
                ss += pf<SQ>(fmaxf(sval[i] - tau, 0.f), inv);
            const float isum = 1.0f / wredsum(ss);

            __syncwarp();
            for (int i = l; i < A; i += 32){
                float r = sval[i] - tau;
                if (r > 0.0f) prow[sidx[i]] = pf<SQ>(r, inv) * isum;
            }
            float ax = 0.f, ay = 0.f;
            #pragma unroll 2
            for (int i = 0; i < A; i++){
                float r = sval[i] - tau;
                if (r > 0.0f){
                    float p = pf<SQ>(r, inv) * isum;
                    float2 vv = *(const float2*)(Vb + (size_t)sidx[i]*DIM + 2*l);
                    ax += p * vv.x; ay += p * vv.y;
                }
            }
            *(float2*)(outrow + 2*l) = make_float2(ax, ay);
        }
    } else {
        // -------- rare overflow fallback: bisect over gmem row --------
        for (int it = 0; it < 27; it++){
            dm *= 0.5f;
            float tm = tau + dm;
            float fm = 0.f;
            for (int j = l; j < SEQ; j += 32)
                fm += pf<SQ>(fmaxf(prow[j] - tm, 0.f), inv);
            fm = wredsum(fm) - 1.0f;
            if (fm * f_lo >= 0.0f) tau = tm;
        }
        float ss = 0.f;
        for (int j = l; j < SEQ; j += 32)
            ss += pf<SQ>(fmaxf(prow[j] - tau, 0.f), inv);
        float isum = 1.0f / wredsum(ss);

        for (int j = l; j < SEQ; j += 32){
            float r = fmaxf(prow[j] - tau, 0.f);
            prow[j] = pf<SQ>(r, inv) * isum;
        }
        __syncwarp();
        float ax = 0.f, ay = 0.f;
        for (int k = 0; k < SEQ; k++){
            float p = prow[k];
            if (p > 0.0f){
                float2 vv = *(const float2*)(Vb + (size_t)k*DIM + 2*l);
                ax += p * vv.x; ay += p * vv.y;
            }
        }
        *(float2*)(outrow + 2*l) = make_float2(ax, ay);
    }
}

__global__ __launch_bounds__(256, 5) void entmax_pv_warp(const float* __restrict__ V,
        const float* __restrict__ alpha_p, float* __restrict__ out, float* __restrict__ P)
{
    __shared__ float sval[8][CAP];
    __shared__ int   sidx[8][CAP];

    const int w   = threadIdx.x >> 5;
    const int l   = threadIdx.x & 31;
    const size_t row = (size_t)blockIdx.x * 8 + w;
    const int bh  = (int)(row >> 11);

    float* prow = P + row * SEQ;
    const float* Vb = V + (size_t)bh * SEQ * DIM;
    float* outrow = out + row * DIM;

    const float am1 = alpha_p[0] - 1.0f;
    const float inv = 1.0f / am1;
    const bool  sq  = fabsf(inv - 2.0f) < 1e-6f;

    if (sq) row_body<true >(prow, Vb, outrow, row, am1, inv, sval[w], sidx[w], l);
    else    row_body<false>(prow, Vb, outrow, row, am1, inv, sval[w], sidx[w], l);
}

// ================================================================
extern "C" void kernel_launch(void* const* d_in, const int* in_sizes, int n_in,
                              void* d_out, int out_size)
{
    const float* Q     = (const float*)d_in[0];
    const float* K     = (const float*)d_in[1];
    const float* V     = (const float*)d_in[2];
    const float* alpha = (const float*)d_in[3];

    float* out = (float*)d_out;                              // [B,H,S,D]
    float* P   = out + (size_t)NBH * SEQ * DIM;              // [B,H,S,S]

    cudaFuncSetAttribute(qk_mma, cudaFuncAttributeMaxDynamicSharedMemorySize, SM_TOTAL);

    split_kernel<<<(2 * NBH * SEQ * DIM / 8) / 256, 256>>>(Q, K);

    dim3 g1(SEQ/128, SEQ/128, NBH);
    qk_mma<<<g1, 256, SM_TOTAL>>>(alpha, P);

    entmax_pv_warp<<<(NBH * SEQ) / 8, 256>>>(V, alpha, out, P);
}

// round 8
// speedup vs baseline: 2.0196x; 1.1737x over previous
#include <cuda_runtime.h>
#include <cuda_bf16.h>
#include <cstdint>
#include <cstddef>

#define BATCH 4
#define HEADS 16
#define SEQ   2048
#define DIM   64
#define NBH   (BATCH*HEADS)
#define CAP   512
#define NEG_INF __int_as_float(0xff800000)

// per-(row, 64-col block) max scratch: [NBH*SEQ][32]
__device__ float g_tmax[(size_t)NBH * SEQ * 32];
// pre-split bf16 hi/lo copies of Q and K (16MB each)
__device__ __nv_bfloat16 g_qhi[(size_t)NBH * SEQ * DIM];
__device__ __nv_bfloat16 g_qlo[(size_t)NBH * SEQ * DIM];
__device__ __nv_bfloat16 g_khi[(size_t)NBH * SEQ * DIM];
__device__ __nv_bfloat16 g_klo[(size_t)NBH * SEQ * DIM];

// ================= helpers =================
__device__ __forceinline__ uint32_t smem_u32(const void* p){
    uint32_t a;
    asm("{ .reg .u64 t; cvta.to.shared.u64 t, %1; cvt.u32.u64 %0, t; }" : "=r"(a) : "l"(p));
    return a;
}
#define SWZ(o) ((o) ^ (((o) >> 3) & 0x70))

__device__ __forceinline__ void ldsm_x4(uint32_t* r, uint32_t addr){
    asm volatile("ldmatrix.sync.aligned.m8n8.x4.shared.b16 {%0,%1,%2,%3}, [%4];"
        : "=r"(r[0]), "=r"(r[1]), "=r"(r[2]), "=r"(r[3]) : "r"(addr));
}
__device__ __forceinline__ void mma_bf16(float* c, const uint32_t* a, const uint32_t* b){
    asm volatile("mma.sync.aligned.m16n8k16.row.col.f32.bf16.bf16.f32 "
        "{%0,%1,%2,%3}, {%4,%5,%6,%7}, {%8,%9}, {%0,%1,%2,%3};"
        : "+f"(c[0]), "+f"(c[1]), "+f"(c[2]), "+f"(c[3])
        : "r"(a[0]), "r"(a[1]), "r"(a[2]), "r"(a[3]), "r"(b[0]), "r"(b[1]));
}

// ================================================================
// Kernel 0: split Q,K fp32 -> bf16 hi + bf16 lo (done ONCE)
// ================================================================
__global__ __launch_bounds__(256) void split_kernel(const float* __restrict__ Q,
                                                    const float* __restrict__ Km)
{
    size_t t = (size_t)blockIdx.x * 256 + threadIdx.x;
    const size_t PER = (size_t)NBH * SEQ * DIM / 8;
    const float* src;
    __nv_bfloat16 *hid, *lod;
    if (t < PER){ src = Q;  hid = g_qhi; lod = g_qlo; }
    else        { t -= PER; src = Km; hid = g_khi; lod = g_klo; }
    const size_t e = t * 8;
    float4 a = *(const float4*)(src + e);
    float4 b = *(const float4*)(src + e + 4);
    float x[8] = {a.x,a.y,a.z,a.w,b.x,b.y,b.z,b.w};
    uint32_t hp[4], lp[4];
    #pragma unroll
    for (int j = 0; j < 4; j++){
        __nv_bfloat162 h2 = __float22bfloat162_rn(make_float2(x[2*j], x[2*j+1]));
        hp[j] = *(uint32_t*)&h2;
        float l0 = x[2*j]   - __low2float(h2);
        float l1 = x[2*j+1] - __high2float(h2);
        __nv_bfloat162 l2 = __float22bfloat162_rn(make_float2(l0, l1));
        lp[j] = *(uint32_t*)&l2;
    }
    *(uint4*)(hid + e) = make_uint4(hp[0], hp[1], hp[2], hp[3]);
    *(uint4*)(lod + e) = make_uint4(lp[0], lp[1], lp[2], lp[3]);
}

// smem layout: 4 tiles of [128 rows][64 bf16 = 128B] SW128-swizzled
#define SM_QHI 0
#define SM_QLO 16384
#define SM_KHI 32768
#define SM_KLO 49152
#define SM_TOTAL 65536

// ================================================================
// Kernel 1 (HMMA): Xa = (QK^T)*scale*(alpha-1), pre-split bf16 inputs.
// ================================================================
__global__ __launch_bounds__(256) void qk_mma(const float* __restrict__ alpha_p,
                                              float* __restrict__ P)
{
    extern __shared__ char smem[];
    const uint32_t sb = smem_u32(smem);
    const int tid = threadIdx.x;

    const int bh = blockIdx.z;
    const int q0 = blockIdx.y * 128;
    const int k0 = blockIdx.x * 128;

    {
        const size_t bq = ((size_t)bh * SEQ + q0) * DIM;
        const size_t bk = ((size_t)bh * SEQ + k0) * DIM;
        const __nv_bfloat16* srcs[4] = {g_qhi + bq, g_qlo + bq, g_khi + bk, g_klo + bk};
        #pragma unroll
        for (int m = 0; m < 4; m++){
            const __nv_bfloat16* s = srcs[m];
            char* dst = smem + m * 16384;
            #pragma unroll
            for (int i = tid; i < 1024; i += 256){
                int row = i >> 3, u = i & 7;
                uint4 v = *(const uint4*)(s + row * 64 + u * 8);
                *(uint4*)(dst + SWZ((uint32_t)(row * 128 + u * 16))) = v;
            }
        }
    }
    __syncthreads();

    const int wid = tid >> 5, l = tid & 31;
    const int mw = wid & 3, nw = wid >> 2;
    const int mrow0 = mw * 32, ncol0 = nw * 64;
    const int sub = l >> 3, win = l & 7;

    float acc[2][8][4];
    #pragma unroll
    for (int mt = 0; mt < 2; mt++)
        #pragma unroll
        for (int nt = 0; nt < 8; nt++)
            #pragma unroll
            for (int j = 0; j < 4; j++) acc[mt][nt][j] = 0.0f;

    #pragma unroll 1
    for (int ks = 0; ks < 4; ks++){
        const int kb = ks * 32;
        uint32_t ah[2][4], al[2][4], bhf[8][2], blf[8][2];

        #pragma unroll
        for (int mt = 0; mt < 2; mt++){
            const int row = mrow0 + mt*16 + win + (sub & 1) * 8;
            const int col = kb + (sub >> 1) * 16;
            const uint32_t off = SWZ((uint32_t)(row * 128 + col));
            ldsm_x4(ah[mt], sb + SM_QHI + off);
            ldsm_x4(al[mt], sb + SM_QLO + off);
        }
        #pragma unroll
        for (int np = 0; np < 4; np++){
            const int row = ncol0 + np*16 + win + (sub >> 1) * 8;
            const int col = kb + (sub & 1) * 16;
            const uint32_t off = SWZ((uint32_t)(row * 128 + col));
            uint32_t r[4];
            ldsm_x4(r, sb + SM_KHI + off);
            bhf[np*2][0] = r[0]; bhf[np*2][1] = r[1];
            bhf[np*2+1][0] = r[2]; bhf[np*2+1][1] = r[3];
            ldsm_x4(r, sb + SM_KLO + off);
            blf[np*2][0] = r[0]; blf[np*2][1] = r[1];
            blf[np*2+1][0] = r[2]; blf[np*2+1][1] = r[3];
        }
        #pragma unroll
        for (int mt = 0; mt < 2; mt++)
            #pragma unroll
            for (int nt = 0; nt < 8; nt++){
                mma_bf16(acc[mt][nt], ah[mt], bhf[nt]);
                mma_bf16(acc[mt][nt], ah[mt], blf[nt]);
                mma_bf16(acc[mt][nt], al[mt], bhf[nt]);
            }
    }

    const float sc = (alpha_p[0] - 1.0f) * 0.125f;
    const int g = l >> 2, tq = l & 3;
    const int kb32 = (k0 + ncol0) >> 6;

    #pragma unroll
    for (int mt = 0; mt < 2; mt++){
        float rm0 = NEG_INF, rm1 = NEG_INF;
        const size_t row0 = (size_t)bh * SEQ + q0 + mrow0 + mt*16 + g;
        float* p0 = P + row0 * SEQ + k0 + ncol0 + tq*2;
        #pragma unroll
        for (int nt = 0; nt < 8; nt++){
            float c0 = acc[mt][nt][0]*sc, c1 = acc[mt][nt][1]*sc;
            float c2 = acc[mt][nt][2]*sc, c3 = acc[mt][nt][3]*sc;
            rm0 = fmaxf(rm0, fmaxf(c0, c1));
            rm1 = fmaxf(rm1, fmaxf(c2, c3));
            *(float2*)(p0 + nt*8)           = make_float2(c0, c1);
            *(float2*)(p0 + nt*8 + 8*SEQ)   = make_float2(c2, c3);
        }
        rm0 = fmaxf(rm0, __shfl_xor_sync(0xffffffffu, rm0, 1));
        rm0 = fmaxf(rm0, __shfl_xor_sync(0xffffffffu, rm0, 2));
        rm1 = fmaxf(rm1, __shfl_xor_sync(0xffffffffu, rm1, 1));
        rm1 = fmaxf(rm1, __shfl_xor_sync(0xffffffffu, rm1, 2));
        if (tq == 0){
            g_tmax[row0 * 32 + kb32]       = rm0;
            g_tmax[(row0 + 8) * 32 + kb32] = rm1;
        }
    }
}

// ================================================================
// Kernel 2: warp/row entmax bisection + sparse PV.
// 64-thread blocks (2 warps = 2 rows) for high occupancy; u16 indices.
// ================================================================
template<bool SQ>
__device__ __forceinline__ float pf(float r, float inv){
    return SQ ? r * r : __powf(r, inv);
}
__device__ __forceinline__ float wredmax(float v){
    #pragma unroll
    for (int o = 16; o; o >>= 1) v = fmaxf(v, __shfl_xor_sync(0xffffffffu, v, o));
    return v;
}
__device__ __forceinline__ float wredsum(float v){
    #pragma unroll
    for (int o = 16; o; o >>= 1) v += __shfl_xor_sync(0xffffffffu, v, o);
    return v;
}

template<bool SQ>
__device__ __forceinline__ void row_body(float* __restrict__ prow,
                                         const float* __restrict__ Vb,
                                         float* __restrict__ outrow,
                                         size_t row, float am1, float inv,
                                         float* __restrict__ sval,
                                         unsigned short* __restrict__ sidx,
                                         int l)
{
    float m = g_tmax[row * 32 + l];
    m = wredmax(m);

    float tau        = m - 1.0f;
    const float t_hi = m - powf(1.0f/(float)SEQ, am1);
    float dm         = t_hi - tau;

    const float4* prow4 = (const float4*)prow;
    int A = 0;
    float fl = 0.0f;
    #pragma unroll
    for (int c = 0; c < 16; c++){
        float4 v = prow4[c*32 + l];
        const int jb = (c*32 + l) * 4;
        float vs[4] = {v.x, v.y, v.z, v.w};
        #pragma unroll
        for (int s = 0; s < 4; s++){
            bool act = vs[s] > tau;
            unsigned mk = __ballot_sync(0xffffffffu, act);
            if (act){
                int pos = A + __popc(mk & ((1u << l) - 1u));
                if (pos < CAP){ sval[pos] = vs[s]; sidx[pos] = (unsigned short)(jb + s); }
                fl += pf<SQ>(vs[s] - tau, inv);
            }
            A += __popc(mk);
        }
    }
    const float f_lo = wredsum(fl) - 1.0f;

    if (A <= CAP){
        float4 z = make_float4(0.f, 0.f, 0.f, 0.f);
        float4* pw = (float4*)prow;
        #pragma unroll
        for (int c = 0; c < 16; c++) pw[c*32 + l] = z;

        // ---- phase 1: 6 iters over full candidate list (smem) ----
        #pragma unroll 1
        for (int it = 0; it < 6; it++){
            dm *= 0.5f;
            float tm = tau + dm;
            float fm = 0.f;
            for (int i = l; i < A; i += 32)
                fm += pf<SQ>(fmaxf(sval[i] - tm, 0.f), inv);
            fm = wredsum(fm) - 1.0f;
            if (fm * f_lo >= 0.0f) tau = tm;
        }

        // ---- recompact (tau monotone; dropped elems stay p=0 forever) ----
        int A2 = 0;
        for (int base = 0; base < A; base += 32){
            int i = base + l;
            float vv = (i < A) ? sval[i] : NEG_INF;
            unsigned short ii = (i < A) ? sidx[i] : 0;
            bool keep = vv > tau;
            unsigned mk = __ballot_sync(0xffffffffu, keep);
            if (keep){
                int pos = A2 + __popc(mk & ((1u << l) - 1u));
                sval[pos] = vv; sidx[pos] = ii;
            }
            A2 += __popc(mk);
        }
        A = A2;
        __syncwarp();

        if (A <= 64){
            // ---- phase 2 from registers ----
            float w0 = (l      < A) ? sval[l]      : NEG_INF;
            float w1 = (l + 32 < A) ? sval[l + 32] : NEG_INF;
            int   j0 = (l      < A) ? (int)sidx[l]      : 0;
            int   j1 = (l + 32 < A) ? (int)sidx[l + 32] : 0;

            #pragma unroll 1
            for (int it = 0; it < 21; it++){
                dm *= 0.5f;
                float tm = tau + dm;
                float a0 = fmaxf(w0 - tm, 0.f), a1 = fmaxf(w1 - tm, 0.f);
                float fm = wredsum(pf<SQ>(a0, inv) + pf<SQ>(a1, inv)) - 1.0f;
                if (fm * f_lo >= 0.0f) tau = tm;
            }
            float a0 = fmaxf(w0 - tau, 0.f), a1 = fmaxf(w1 - tau, 0.f);
            float p0 = pf<SQ>(a0, inv), p1 = pf<SQ>(a1, inv);
            const float isum = 1.0f / wredsum(p0 + p1);
            p0 *= isum; p1 *= isum;

            __syncwarp();
            if (p0 > 0.0f) prow[j0] = p0;
            if (p1 > 0.0f) prow[j1] = p1;
            sval[l]      = p0;
            sval[l + 32] = p1;
            __syncwarp();

            float ax = 0.f, ay = 0.f;
            #pragma unroll 4
            for (int i = 0; i < A; i++){
                float p = sval[i];
                float2 vv = *(const float2*)(Vb + (size_t)sidx[i]*DIM + 2*l);
                ax += p * vv.x; ay += p * vv.y;
            }
            *(float2*)(outrow + 2*l) = make_float2(ax, ay);
        } else {
            // ---- phase 2 general (smem) ----
            #pragma unroll 1
            for (int it = 0; it < 21; it++){
                dm *= 0.5f;
                float tm = tau + dm;
                float fm = 0.f;
                for (int i = l; i < A; i += 32)
                    fm += pf<SQ>(fmaxf(sval[i] - tm, 0.f), inv);
                fm = wredsum(fm) - 1.0f;
                if (fm * f_lo >= 0.0f) tau = tm;
            }
            float ss = 0.f;
            for (int i = l; i < A; i += 32)
                ss += pf<SQ>(fmaxf(sval[i] - tau, 0.f), inv);
            const float isum = 1.0f / wredsum(ss);

            __syncwarp();
            for (int i = l; i < A; i += 32){
                float r = sval[i] - tau;
                if (r > 0.0f) prow[sidx[i]] = pf<SQ>(r, inv) * isum;
            }
            float ax = 0.f, ay = 0.f;
            #pragma unroll 2
            for (int i = 0; i < A; i++){
                float r = sval[i] - tau;
                if (r > 0.0f){
                    float p = pf<SQ>(r, inv) * isum;
                    float2 vv = *(const float2*)(Vb + (size_t)sidx[i]*DIM + 2*l);
                    ax += p * vv.x; ay += p * vv.y;
                }
            }
            *(float2*)(outrow + 2*l) = make_float2(ax, ay);
        }
    } else {
        // -------- rare overflow fallback: bisect over gmem row --------
        for (int it = 0; it < 27; it++){
            dm *= 0.5f;
            float tm = tau + dm;
            float fm = 0.f;
            for (int j = l; j < SEQ; j += 32)
                fm += pf<SQ>(fmaxf(prow[j] - tm, 0.f), inv);
            fm = wredsum(fm) - 1.0f;
            if (fm * f_lo >= 0.0f) tau = tm;
        }
        float ss = 0.f;
        for (int j = l; j < SEQ; j += 32)
            ss += pf<SQ>(fmaxf(prow[j] - tau, 0.f), inv);
        float isum = 1.0f / wredsum(ss);

        for (int j = l; j < SEQ; j += 32){
            float r = fmaxf(prow[j] - tau, 0.f);
            prow[j] = pf<SQ>(r, inv) * isum;
        }
        __syncwarp();
        float ax = 0.f, ay = 0.f;
        for (int k = 0; k < SEQ; k++){
            float p = prow[k];
            if (p > 0.0f){
                float2 vv = *(const float2*)(Vb + (size_t)k*DIM + 2*l);
                ax += p * vv.x; ay += p * vv.y;
            }
        }
        *(float2*)(outrow + 2*l) = make_float2(ax, ay);
    }
}

__global__ __launch_bounds__(64, 28) void entmax_pv_warp(const float* __restrict__ V,
        const float* __restrict__ alpha_p, float* __restrict__ out, float* __restrict__ P)
{
    __shared__ float          sval[2][CAP];
    __shared__ unsigned short sidx[2][CAP];

    const int w   = threadIdx.x >> 5;
    const int l   = threadIdx.x & 31;
    const size_t row = (size_t)blockIdx.x * 2 + w;
    const int bh  = (int)(row >> 11);

    float* prow = P + row * SEQ;
    const float* Vb = V + (size_t)bh * SEQ * DIM;
    float* outrow = out + row * DIM;

    const float am1 = alpha_p[0] - 1.0f;
    const float inv = 1.0f / am1;
    const bool  sq  = fabsf(inv - 2.0f) < 1e-6f;

    if (sq) row_body<true >(prow, Vb, outrow, row, am1, inv, sval[w], sidx[w], l);
    else    row_body<false>(prow, Vb, outrow, row, am1, inv, sval[w], sidx[w], l);
}

// ================================================================
extern "C" void kernel_launch(void* const* d_in, const int* in_sizes, int n_in,
                              void* d_out, int out_size)
{
    const float* Q     = (const float*)d_in[0];
    const float* K     = (const float*)d_in[1];
    const float* V     = (const float*)d_in[2];
    const float* alpha = (const float*)d_in[3];

    float* out = (float*)d_out;                              // [B,H,S,D]
    float* P   = out + (size_t)NBH * SEQ * DIM;              // [B,H,S,S]

    cudaFuncSetAttribute(qk_mma, cudaFuncAttributeMaxDynamicSharedMemorySize, SM_TOTAL);

    split_kernel<<<(2 * NBH * SEQ * DIM / 8) / 256, 256>>>(Q, K);

    dim3 g1(SEQ/128, SEQ/128, NBH);
    qk_mma<<<g1, 256, SM_TOTAL>>>(alpha, P);

    entmax_pv_warp<<<(NBH * SEQ) / 2, 64>>>(V, alpha, out, P);
}